// round 2
// baseline (speedup 1.0000x reference)
#include <cuda_runtime.h>
#include <cstdint>

#define BB 4096
#define NN 32
#define HH 128
#define LL 16
#define AA 10
#define HYBN 3
#define NE 62

// output layout: tuple flattened in return order, float32
#define NF_OFF    0
#define ALP_OFF   (BB*NN*17)              // 2228224
#define HLP_OFF   (ALP_OFF + BB)          // 2232320
#define EATTR_OFF (HLP_OFF + BB)          // 2236416
#define EMASK_OFF (EATTR_OFF + BB*NE*4)   // 3252224

// scratch (__device__ global: allocation-free)
__device__ float d_X[BB*HH];

__constant__ float c_maxval[AA] = {4.f,3.f,2.f,1.f,4.f,2.f,6.f,1.f,4.f,4.f};

// ---------------- Threefry-2x32 (exact JAX implementation) ----------------
__host__ __device__ __forceinline__ uint32_t rotl32(uint32_t x, int d) {
    return (x << d) | (x >> (32 - d));
}
__host__ __device__ inline void threefry2x32(uint32_t k0, uint32_t k1,
                                             uint32_t x0, uint32_t x1,
                                             uint32_t& o0, uint32_t& o1) {
    uint32_t ks2 = k0 ^ k1 ^ 0x1BD11BDAu;
#define TFR(r) { x0 += x1; x1 = rotl32(x1, (r)); x1 ^= x0; }
    x0 += k0; x1 += k1;
    TFR(13) TFR(15) TFR(26) TFR(6)   x0 += k1;  x1 += ks2 + 1u;
    TFR(17) TFR(29) TFR(16) TFR(24)  x0 += ks2; x1 += k0 + 2u;
    TFR(13) TFR(15) TFR(26) TFR(6)   x0 += k0;  x1 += k1 + 3u;
    TFR(17) TFR(29) TFR(16) TFR(24)  x0 += k1;  x1 += ks2 + 4u;
    TFR(13) TFR(15) TFR(26) TFR(6)   x0 += ks2; x1 += k0 + 5u;
#undef TFR
    o0 = x0; o1 = x1;
}

// partitionable-mode 32-bit random bits for flat element index idx (< 2^32):
// (b1,b2) = threefry(key, (0, idx)); bits = b1 ^ b2
__device__ __forceinline__ uint32_t rbits32(uint32_t k0, uint32_t k1, uint32_t idx) {
    uint32_t o0, o1;
    threefry2x32(k0, k1, 0u, idx, o0, o1);
    return o0 ^ o1;
}

__device__ __forceinline__ float bits_to_u01(uint32_t b) {
    return __uint_as_float((b >> 9) | 0x3f800000u) - 1.0f;
}

// gumbel draw matching jax: u = max(mn, u01*span + mn); g = -log(-log(u))
__device__ __forceinline__ float gumbel_draw(uint32_t k0, uint32_t k1, uint32_t idx,
                                             float mn, float span) {
    float u = bits_to_u01(rbits32(k0, k1, idx));
    u = fmaxf(mn, __fadd_rn(__fmul_rn(u, span), mn));
    return -logf(-logf(u));
}

// ---------------- MLP chain (the node-uniform GAT stack collapsed to [B,H]) ----------------
#define BROWS 28
__global__ void __launch_bounds__(256) mlp_kernel(
    const float* __restrict__ noise, const float* __restrict__ w1,
    const float* __restrict__ b1, const float* __restrict__ gw,
    const float* __restrict__ gb) {
    __shared__ float Ws[HH * HH];
    __shared__ float xs[BROWS * HH];
    const int tid = threadIdx.x;
    const int col = tid & 127;
    const int rh = tid >> 7;          // 0 or 1 -> rows rh*14 .. rh*14+13
    const int base = blockIdx.x * BROWS;

    // load input rows (noise)
    for (int i = tid; i < BROWS * HH; i += 256) {
        int r = i >> 7, g = base + r;
        xs[i] = (g < BB) ? noise[g * HH + (i & 127)] : 0.f;
    }

    for (int layer = 0; layer <= LL; layer++) {
        const float* Wsrc = (layer == 0) ? w1 : gw + (size_t)(layer - 1) * HH * HH;
        const float* bsrc = (layer == 0) ? b1 : gb + (layer - 1) * HH;
        for (int i = tid; i < HH * HH; i += 256) Ws[i] = Wsrc[i];
        __syncthreads();

        float acc[14];
        #pragma unroll
        for (int r = 0; r < 14; r++) acc[r] = bsrc[col];
        const float* xrow = &xs[(rh * 14) * HH];
        #pragma unroll 2
        for (int k = 0; k < HH; k += 4) {
            float w0 = Ws[(k + 0) * HH + col];
            float w1v = Ws[(k + 1) * HH + col];
            float w2 = Ws[(k + 2) * HH + col];
            float w3 = Ws[(k + 3) * HH + col];
            #pragma unroll
            for (int r = 0; r < 14; r++) {
                const float4 xv = *(const float4*)&xrow[r * HH + k];
                acc[r] = fmaf(xv.x, w0, acc[r]);
                acc[r] = fmaf(xv.y, w1v, acc[r]);
                acc[r] = fmaf(xv.z, w2, acc[r]);
                acc[r] = fmaf(xv.w, w3, acc[r]);
            }
        }
        float res[14];
        #pragma unroll
        for (int r = 0; r < 14; r++) res[r] = xrow[r * HH + col];
        __syncthreads();
        #pragma unroll
        for (int r = 0; r < 14; r++) {
            float v = (layer == 0) ? acc[r] : acc[r] + res[r];
            xs[(rh * 14 + r) * HH + col] = fmaxf(v, 0.f);
        }
        __syncthreads();
    }

    #pragma unroll
    for (int r = 0; r < 14; r++) {
        int g = base + rh * 14 + r;
        if (g < BB) d_X[(size_t)g * HH + col] = xs[(rh * 14 + r) * HH + col];
    }
}

// ---------------- Heads: logits, inline sampling, node features, edges ----------------
__global__ void __launch_bounds__(64) heads_kernel(
    const float* __restrict__ w_atom, const float* __restrict__ b_atom,
    const float* __restrict__ w_hyb,  const float* __restrict__ b_hyb,
    const float* __restrict__ w_deg,  const float* __restrict__ b_deg,
    const float* __restrict__ w_chg,  const float* __restrict__ b_chg,
    const float* __restrict__ w_arom, const float* __restrict__ b_arom,
    const float* __restrict__ w_eex,  const float* __restrict__ b_eex,
    const float* __restrict__ w_ety,  const float* __restrict__ b_ety,
    uint32_t a_k0, uint32_t a_k1, uint32_t h_k0, uint32_t h_k1,
    uint32_t r_k0, uint32_t r_k1, uint32_t e_k0, uint32_t e_k1,
    float mn, float span,
    float* __restrict__ out) {
    const int b = blockIdx.x;
    const int tid = threadIdx.x;
    __shared__ float xv[HH];
    __shared__ float alog[AA], alp[AA], hlog[HYBN], hlp[HYBN];
    __shared__ float sdeg, schg, sarom;
    __shared__ float nf[NN][18];

    for (int i = tid; i < HH; i += 64) xv[i] = d_X[(size_t)b * HH + i];
    __syncthreads();

    if (tid < 16) {
        float acc;
        if (tid < AA) {
            acc = b_atom[tid];
            for (int k = 0; k < HH; k++) acc = fmaf(xv[k], w_atom[k * AA + tid], acc);
            alog[tid] = acc;
        } else if (tid < 13) {
            int j = tid - 10;
            acc = b_hyb[j];
            for (int k = 0; k < HH; k++) acc = fmaf(xv[k], w_hyb[k * HYBN + j], acc);
            hlog[j] = acc;
        } else if (tid == 13) {
            acc = b_deg[0];
            for (int k = 0; k < HH; k++) acc = fmaf(xv[k], w_deg[k], acc);
            sdeg = 1.f / (1.f + expf(-acc));
        } else if (tid == 14) {
            acc = b_chg[0];
            for (int k = 0; k < HH; k++) acc = fmaf(xv[k], w_chg[k], acc);
            schg = tanhf(acc);
        } else {
            acc = b_arom[0];
            for (int k = 0; k < HH; k++) acc = fmaf(xv[k], w_arom[k], acc);
            sarom = 1.f / (1.f + expf(-acc));
        }
    }
    __syncthreads();

    if (tid == 0) {
        float m = alog[0];
        for (int a = 1; a < AA; a++) m = fmaxf(m, alog[a]);
        float s = 0.f;
        for (int a = 0; a < AA; a++) s += expf(alog[a] - m);
        float lse = logf(s);
        for (int a = 0; a < AA; a++) alp[a] = alog[a] - m - lse;
        m = hlog[0];
        for (int a = 1; a < HYBN; a++) m = fmaxf(m, hlog[a]);
        s = 0.f;
        for (int a = 0; a < HYBN; a++) s += expf(hlog[a] - m);
        lse = logf(s);
        for (int a = 0; a < HYBN; a++) hlp[a] = hlog[a] - m - lse;
    }
    __syncthreads();

    // ---- node phase (threads 0..31) ----
    float myalp = 0.f, myhlp = 0.f;
    if (tid < NN) {
        const int n = tid;
        const uint32_t node = (uint32_t)(b * NN + n);
        int ai = 0; float best = -1e30f;
        #pragma unroll
        for (int a = 0; a < AA; a++) {
            float g = gumbel_draw(a_k0, a_k1, node * AA + a, mn, span);
            float v = alog[a] + g;
            if (v > best) { best = v; ai = a; }
        }
        int hi = 0; float bh = -1e30f;
        #pragma unroll
        for (int a = 0; a < HYBN; a++) {
            float g = gumbel_draw(h_k0, h_k1, node * HYBN + a, mn, span);
            float v = hlog[a] + g;
            if (v > bh) { bh = v; hi = a; }
        }
        float u = bits_to_u01(rbits32(r_k0, r_k1, node));
        float arom = (u < sarom) ? 1.f : 0.f;
        float val = c_maxval[ai] / 5.0f;

        float row[17];
        #pragma unroll
        for (int f = 0; f < AA; f++) row[f] = (f == ai) ? 1.f : 0.f;
        row[10] = sdeg;
        row[11] = schg;
        #pragma unroll
        for (int f = 0; f < HYBN; f++) row[12 + f] = (f == hi) ? 1.f : 0.f;
        row[15] = arom;
        row[16] = val;

        float* o = out + NF_OFF + (size_t)node * 17;
        #pragma unroll
        for (int f = 0; f < 17; f++) { nf[n][f] = row[f]; o[f] = row[f]; }

        myalp = alp[ai];
        myhlp = hlp[hi];
    }
    if (tid < 32) {
        #pragma unroll
        for (int off = 16; off > 0; off >>= 1) {
            myalp += __shfl_down_sync(0xffffffffu, myalp, off);
            myhlp += __shfl_down_sync(0xffffffffu, myhlp, off);
        }
        if (tid == 0) {
            out[ALP_OFF + b] = myalp / 32.f;
            out[HLP_OFF + b] = myhlp / 32.f;
        }
    }
    __syncthreads();

    // ---- edge phase (threads 0..61) ----
    if (tid < NE) {
        const int e = tid;
        const int un = (e < 31) ? e : e - 30;       // eu
        const int vn = (e < 31) ? e + 1 : e - 31;   // ev
        float elog = b_eex[0];
        float tl[4];
        #pragma unroll
        for (int t = 0; t < 4; t++) tl[t] = b_ety[t];
        #pragma unroll
        for (int f = 0; f < 17; f++) {
            float a1 = nf[un][f];
            float a2 = nf[vn][f];
            elog = fmaf(a1, w_eex[f], elog);
            elog = fmaf(a2, w_eex[17 + f], elog);
            #pragma unroll
            for (int t = 0; t < 4; t++) {
                tl[t] = fmaf(a1, w_ety[f * 4 + t], tl[t]);
                tl[t] = fmaf(a2, w_ety[(17 + f) * 4 + t], tl[t]);
            }
        }
        float p = 1.f / (1.f + expf(-elog));
        out[EMASK_OFF + (size_t)b * NE + e] = (p > 0.5f) ? 1.f : 0.f;

        const uint32_t ebase = (uint32_t)(b * NE + e) * 4u;
        int ti = 0; float bt = -1e30f;
        #pragma unroll
        for (int t = 0; t < 4; t++) {
            float g = gumbel_draw(e_k0, e_k1, ebase + t, mn, span);
            float v = tl[t] + g;
            if (v > bt) { bt = v; ti = t; }
        }
        float* oe = out + EATTR_OFF + (size_t)ebase;
        #pragma unroll
        for (int t = 0; t < 4; t++) oe[t] = (t == ti) ? 1.f : 0.f;
    }
}

// ---------------- launch ----------------
extern "C" void kernel_launch(void* const* d_in, const int* in_sizes, int n_in,
                              void* d_out, int out_size) {
    const float* noise  = (const float*)d_in[0];
    const float* w1     = (const float*)d_in[1];
    const float* b1     = (const float*)d_in[2];
    const float* gat_w  = (const float*)d_in[3];
    const float* gat_b  = (const float*)d_in[4];
    // d_in[5] att_src, d_in[6] att_dst: numerically irrelevant (node-uniform collapse)
    const float* w_atom = (const float*)d_in[7];
    const float* b_atom = (const float*)d_in[8];
    const float* w_hyb  = (const float*)d_in[9];
    const float* b_hyb  = (const float*)d_in[10];
    const float* w_deg  = (const float*)d_in[11];
    const float* b_deg  = (const float*)d_in[12];
    const float* w_chg  = (const float*)d_in[13];
    const float* b_chg  = (const float*)d_in[14];
    const float* w_arom = (const float*)d_in[15];
    const float* b_arom = (const float*)d_in[16];
    const float* w_eex  = (const float*)d_in[17];
    const float* b_eex  = (const float*)d_in[18];
    const float* w_ety  = (const float*)d_in[19];
    const float* b_ety  = (const float*)d_in[20];
    float* out = (float*)d_out;

    // jax.random.key(42) -> (0, 42)
    // partitionable split(key, 4): sk[i] = threefry(key, (0, i)) -> (o0, o1)
    uint32_t sk[4][2];
    for (uint32_t i = 0; i < 4; i++)
        threefry2x32(0u, 42u, 0u, i, sk[i][0], sk[i][1]);

    const float mn = 1e-6f;
    const float mx = (float)(1.0 - 1e-6);
    const float span = mx - mn;

    mlp_kernel<<<148, 256>>>(noise, w1, b1, gat_w, gat_b);

    heads_kernel<<<BB, 64>>>(w_atom, b_atom, w_hyb, b_hyb, w_deg, b_deg,
                             w_chg, b_chg, w_arom, b_arom, w_eex, b_eex,
                             w_ety, b_ety,
                             sk[0][0], sk[0][1], sk[1][0], sk[1][1],
                             sk[2][0], sk[2][1], sk[3][0], sk[3][1],
                             mn, span, out);
}